// round 13
// baseline (speedup 1.0000x reference)
#include <cuda_runtime.h>
#include <cuda_fp16.h>
#include <cstdint>

// ---------------- problem constants ----------------
constexpr int Dd   = 768;
constexpr int RS   = 256 * 768;            // row stride in floats (B*D)
constexpr int TEXT_ELEMS   = 77 * 256 * 768;
constexpr int VISION_ELEMS = 576 * 256 * 768;

// S / A scratch in gmem: [b][m=77][row container 576 words]
// before k2: fp32 logits; after k2: fp16 half2 pairs in [0,288) of each row
__device__ float g_S[256 * 77 * 576];

__device__ __forceinline__ float ex2f(float x) {
    float y; asm("ex2.approx.f32 %0, %1;" : "=f"(y) : "f"(x)); return y;
}

// split a float2 into hi (fp16x2) and lo (fp16x2 of residual), packed as u32
__device__ __forceinline__ void split2(float2 x, uint32_t& h, uint32_t& l) {
    __half hx = __float2half_rn(x.x), hy = __float2half_rn(x.y);
    __half lx = __float2half_rn(x.x - __half2float(hx));
    __half ly = __float2half_rn(x.y - __half2float(hy));
    h = (uint32_t)__half_as_ushort(hx) | ((uint32_t)__half_as_ushort(hy) << 16);
    l = (uint32_t)__half_as_ushort(lx) | ((uint32_t)__half_as_ushort(ly) << 16);
}

__device__ __forceinline__ uint32_t pack2(float2 x) {
    __half hx = __float2half_rn(x.x), hy = __float2half_rn(x.y);
    return (uint32_t)__half_as_ushort(hx) | ((uint32_t)__half_as_ushort(hy) << 16);
}

// fp16 m16n8k16, fp32 accumulate
__device__ __forceinline__ void mma16(float* c,
                                      uint32_t a0, uint32_t a1, uint32_t a2, uint32_t a3,
                                      uint32_t b0, uint32_t b1) {
    asm volatile(
        "mma.sync.aligned.m16n8k16.row.col.f32.f16.f16.f32 "
        "{%0,%1,%2,%3}, {%4,%5,%6,%7}, {%8,%9}, {%0,%1,%2,%3};\n"
        : "+f"(c[0]), "+f"(c[1]), "+f"(c[2]), "+f"(c[3])
        : "r"(a0), "r"(a1), "r"(a2), "r"(a3), "r"(b0), "r"(b1));
}

#define CP_ASYNC16(saddr, gptr) \
    asm volatile("cp.async.cg.shared.global [%0], [%1], 16;" :: "r"(saddr), "l"(gptr))
#define CP_COMMIT() asm volatile("cp.async.commit_group;")
#define CP_WAIT1()  asm volatile("cp.async.wait_group 1;" ::: "memory")
#define CP_WAIT0()  asm volatile("cp.async.wait_group 0;" ::: "memory")

// ============== Kernel 1: S = T V^T (3xFP16), cp.async 2-deep pipeline ==============
// grid 768 = (b, nt). M=96(77 real) x N=192 per CTA, 512 thr = 16 warps (2x8), 48x24 tile.
// k-chunk = 32 floats (16 pairs).
// smem (words): halfbuf[2] x 11520 (TH 0 | TL 1920 | VH 3840 | VL 7680) at 0, 11520;
//               raw ring[3] x 8608 at 23040 (T float4s [0,616), V float4s [616,2152)).
constexpr int K1_HB    = 11520;
constexpr int K1_RAW   = 23040;
constexpr int K1_SLOT  = 8608;
constexpr int K1_WORDS = K1_RAW + 3 * K1_SLOT;       // 48864
constexpr int K1_BYTES = K1_WORDS * 4;               // 195456 B

extern __shared__ float smdyn[];

__global__ __launch_bounds__(512, 1)
void k1_gemm1(const float* __restrict__ text, const float* __restrict__ vision) {
    uint32_t* smu = (uint32_t*)smdyn;
    const int b  = blockIdx.x / 3;
    const int nt = blockIdx.x % 3;
    const int nb = nt * 192;
    const float* tb = text + (size_t)b * Dd;
    const float* vb = vision + (size_t)b * Dd;

    uint32_t sbase;
    asm("{ .reg .u64 t; cvta.to.shared.u64 t, %1; cvt.u32.u64 %0, t; }"
        : "=r"(sbase) : "l"(smdyn));

    const int tid  = threadIdx.x;
    const int w    = tid >> 5;    // 0..15
    const int lane = tid & 31;
    const int wm   = w >> 3;      // 0..1
    const int wn   = w & 7;       // 0..7
    const int g    = lane >> 2;
    const int c    = lane & 3;

    float acc[3][3][4];
    #pragma unroll
    for (int mt = 0; mt < 3; ++mt)
        #pragma unroll
        for (int nc = 0; nc < 3; ++nc)
            #pragma unroll
            for (int q = 0; q < 4; ++q) acc[mt][nc][q] = 0.f;

    // ---- cp.async issue for one chunk: thread i copies float4 #i of T and V ----
    // slot layout (float4 units): T at [0,616), V at [616,2152)
    auto issue_chunk = [&](int cc, int slot) {
        const int d0 = cc * 32;
        const uint32_t sraw = sbase + (K1_RAW + slot * K1_SLOT) * 4;
        #pragma unroll
        for (int q = 0; q < 2; ++q) {
            int i = tid + 512 * q;                 // T: 616 float4
            if (i < 616) {
                int m = i >> 3, j4 = i & 7;
                CP_ASYNC16(sraw + 16 * i, tb + (size_t)m * RS + d0 + 4 * j4);
            }
        }
        #pragma unroll
        for (int q = 0; q < 3; ++q) {
            int i = tid + 512 * q;                 // V: 1536 float4
            int m = i >> 3, j4 = i & 7;
            CP_ASYNC16(sraw + (616 + i) * 16, vb + (size_t)(nb + m) * RS + d0 + 4 * j4);
        }
        CP_COMMIT();
    };

    // prologue: 2 chunks in flight
    issue_chunk(0, 0);
    issue_chunk(1, 1);

    int slot = 0;
    for (int dc = 0; dc < 24; ++dc) {
        if (dc < 23) CP_WAIT1(); else CP_WAIT0();

        const int bo = (dc & 1) * K1_HB;
        const int rawb = K1_RAW + slot * K1_SLOT;

        // convert raw fp32 -> hi/lo half tiles (own-thread data only)
        #pragma unroll
        for (int q = 0; q < 2; ++q) {
            int i = tid + 512 * q;
            if (i < 616) {
                int m = i >> 3, j4 = i & 7;
                float4 x = *(float4*)&smdyn[rawb + 4 * i];
                uint32_t h0, l0, h1, l1;
                split2(make_float2(x.x, x.y), h0, l0);
                split2(make_float2(x.z, x.w), h1, l1);
                *(uint2*)&smu[bo + m * 20 + 2 * j4] = make_uint2(h0, h1);
                *(uint2*)&smu[bo + 1920 + m * 20 + 2 * j4] = make_uint2(l0, l1);
            }
        }
        #pragma unroll
        for (int q = 0; q < 3; ++q) {
            int i = tid + 512 * q;
            int m = i >> 3, j4 = i & 7;
            float4 x = *(float4*)&smdyn[rawb + 2464 + 4 * i];
            uint32_t h0, l0, h1, l1;
            split2(make_float2(x.x, x.y), h0, l0);
            split2(make_float2(x.z, x.w), h1, l1);
            *(uint2*)&smu[bo + 3840 + m * 20 + 2 * j4] = make_uint2(h0, h1);
            *(uint2*)&smu[bo + 7680 + m * 20 + 2 * j4] = make_uint2(l0, l1);
        }

        // issue chunk dc+2 into slot (slot+2)%3
        if (dc < 22) {
            int s2 = slot + 2; if (s2 >= 3) s2 -= 3;
            issue_chunk(dc + 2, s2);
        }

        __syncthreads();   // single barrier per interval

        // mma chunk dc from halfbuf[dc&1]
        #pragma unroll
        for (int kk = 0; kk < 2; ++kk) {
            uint32_t bh0[3], bh1[3], bl0[3], bl1[3];
            #pragma unroll
            for (int nc = 0; nc < 3; ++nc) {
                int row = wn * 24 + nc * 8 + g;
                int ba  = bo + row * 20 + kk * 8 + c;
                bh0[nc] = smu[ba + 3840];     bh1[nc] = smu[ba + 3840 + 4];
                bl0[nc] = smu[ba + 7680];     bl1[nc] = smu[ba + 7680 + 4];
            }
            #pragma unroll
            for (int mt = 0; mt < 3; ++mt) {
                int r  = wm * 48 + mt * 16 + g;
                int aa = bo + r * 20 + kk * 8 + c;
                uint32_t ah0 = smu[aa];
                uint32_t ah1 = smu[aa + 8 * 20];
                uint32_t ah2 = smu[aa + 4];
                uint32_t ah3 = smu[aa + 8 * 20 + 4];
                uint32_t al0 = smu[aa + 1920];
                uint32_t al1 = smu[aa + 1920 + 8 * 20];
                uint32_t al2 = smu[aa + 1920 + 4];
                uint32_t al3 = smu[aa + 1920 + 8 * 20 + 4];
                #pragma unroll
                for (int nc = 0; nc < 3; ++nc) {
                    mma16(acc[mt][nc], ah0, ah1, ah2, ah3, bh0[nc], bh1[nc]);
                    mma16(acc[mt][nc], ah0, ah1, ah2, ah3, bl0[nc], bl1[nc]);
                    mma16(acc[mt][nc], al0, al1, al2, al3, bh0[nc], bh1[nc]);
                }
            }
        }

        slot = slot + 1; if (slot >= 3) slot -= 3;
    }

    // epilogue: store S tile (fp32) to gmem scratch
    #pragma unroll
    for (int mt = 0; mt < 3; ++mt) {
        int r0 = wm * 48 + mt * 16 + g, r1 = r0 + 8;
        #pragma unroll
        for (int nc = 0; nc < 3; ++nc) {
            int col = nb + wn * 24 + nc * 8 + 2 * c;
            if (r0 < 77)
                *(float2*)&g_S[((size_t)b * 77 + r0) * 576 + col] =
                    make_float2(acc[mt][nc][0], acc[mt][nc][1]);
            if (r1 < 77)
                *(float2*)&g_S[((size_t)b * 77 + r1) * 576 + col] =
                    make_float2(acc[mt][nc][2], acc[mt][nc][3]);
        }
    }
}

// ===== Kernel 2: softmax (temp 0.07), in place; writes A as plain fp16 pairs =====
__global__ __launch_bounds__(256, 8)
void k2_softmax() {
    const int w = threadIdx.x >> 5, lane = threadIdx.x & 31;
    const int row = blockIdx.x * 8 + w;       // 0..19711
    float* p = &g_S[(size_t)row * 576];
    uint32_t* pu = (uint32_t*)p;
    const float SCL = 20.60992915555662f;     // log2(e)/0.07

    float v[18];
    float mx = -1e30f;
    #pragma unroll
    for (int j = 0; j < 18; ++j) { v[j] = p[lane + 32 * j]; mx = fmaxf(mx, v[j]); }
    #pragma unroll
    for (int o = 16; o > 0; o >>= 1) mx = fmaxf(mx, __shfl_xor_sync(0xffffffffu, mx, o));
    float sum = 0.f;
    #pragma unroll
    for (int j = 0; j < 18; ++j) { v[j] = ex2f((v[j] - mx) * SCL); sum += v[j]; }
    #pragma unroll
    for (int o = 16; o > 0; o >>= 1) sum += __shfl_xor_sync(0xffffffffu, sum, o);
    const float rinv = 1.0f / sum;

    // lane <-> pair transpose via shfl with warp-uniform register indices.
    #pragma unroll
    for (int q = 0; q < 9; ++q) {
        int s0 = (2 * lane) & 31;
        int s1 = (2 * lane + 1) & 31;
        float ea = __shfl_sync(0xffffffffu, v[2 * q],     s0);
        float eb = __shfl_sync(0xffffffffu, v[2 * q + 1], s0);
        float fa = __shfl_sync(0xffffffffu, v[2 * q],     s1);
        float fb = __shfl_sync(0xffffffffu, v[2 * q + 1], s1);
        float x = (lane < 16) ? ea : eb;
        float y = (lane < 16) ? fa : fb;
        pu[lane + 32 * q] = pack2(make_float2(x * rinv, y * rinv));  // fp16 plane [0,288)
    }
}

// ====== Kernel 3: O = A V (2xFP16: ah*bh + ah*bl), A fp16, d-tile 192, double-buffered ======
constexpr int A_STR   = 292;
constexpr int K3_VB   = 77 * A_STR + 12;       // 22496 (V buffers start)
constexpr int K3_BUF  = 6400;
constexpr int K3_BYTES = (K3_VB + 2 * K3_BUF) * 4;   // 141184 B

__global__ __launch_bounds__(512, 1)
void k3_gemm2(const float* __restrict__ vision, float* __restrict__ out) {
    uint32_t* smu = (uint32_t*)smdyn;
    const int b = blockIdx.x;
    const float* vb = vision + (size_t)b * Dd;
    float* ob = out + (size_t)b * Dd;

    const int tid  = threadIdx.x;
    const int w    = tid >> 5;    // 0..15  (n-pair owner for staging)
    const int lane = tid & 31;
    const int wm   = w >> 3;
    const int wn   = w & 7;
    const int g    = lane >> 2;
    const int c    = lane & 3;

    // load fp16 A into smem (coalesced float4): 77 rows x 72 float4
    {
        const float4* src = (const float4*)&g_S[(size_t)b * 77 * 576];
        #pragma unroll
        for (int q = 0; q < 11; ++q) {
            int i = tid + 512 * q;
            if (i < 5544) {                      // 77 * 72
                int m = i / 72, f = i % 72;
                *(float4*)&smdyn[m * A_STR + 4 * f] = src[(size_t)m * 144 + f];
            }
        }
    }

    int arow[3][2];
    #pragma unroll
    for (int mt = 0; mt < 3; ++mt) {
        int r0 = wm * 48 + mt * 16 + g;
        int r1 = r0 + 8;
        arow[mt][0] = (r0 > 76 ? 76 : r0) * A_STR;
        arow[mt][1] = (r1 > 76 ? 76 : r1) * A_STR;
    }

    float acc[3][3][4];
    #pragma unroll
    for (int mt = 0; mt < 3; ++mt)
        #pragma unroll
        for (int d8 = 0; d8 < 3; ++d8)
            #pragma unroll
            for (int q = 0; q < 4; ++q) acc[mt][d8][q] = 0.f;

    float pv0[6], pv1[6];
    {
        const float* r0p = vb + (size_t)(2 * w) * RS;
        const float* r1p = vb + (size_t)(2 * w + 1) * RS;
        #pragma unroll
        for (int it = 0; it < 6; ++it) {
            int d = lane + 32 * it;
            pv0[it] = r0p[d];
            pv1[it] = r1p[d];
        }
    }

    int dt = 0, ch = 0;
    for (int s = 0; s < 72; ++s) {
        const int bo = K3_VB + (s & 1) * K3_BUF;

        #pragma unroll
        for (int it = 0; it < 6; ++it) {
            int d = lane + 32 * it;
            uint32_t h, l;
            split2(make_float2(pv0[it], pv1[it]), h, l);
            smu[bo + w * 200 + d] = h;
            smu[bo + 3200 + w * 200 + d] = l;
        }

        int ndt = dt, nch = ch + 1;
        if (nch == 18) { nch = 0; ndt = dt + 1; }
        if (s < 71) {
            const float* r0p = vb + (size_t)(nch * 32 + 2 * w) * RS + ndt * 192;
            const float* r1p = r0p + RS;
            #pragma unroll
            for (int it = 0; it < 6; ++it) {
                int d = lane + 32 * it;
                pv0[it] = r0p[d];
                pv1[it] = r1p[d];
            }
        }

        __syncthreads();

        #pragma unroll
        for (int kk = 0; kk < 2; ++kk) {
            uint32_t bh0[3], bh1[3], bl0[3], bl1[3];
            #pragma unroll
            for (int d8 = 0; d8 < 3; ++d8) {
                int col = wn * 24 + d8 * 8 + g;
                int pa  = bo + (kk * 8 + c) * 200 + col;
                bh0[d8] = smu[pa];            bh1[d8] = smu[pa + 4 * 200];
                bl0[d8] = smu[pa + 3200];     bl1[d8] = smu[pa + 3200 + 4 * 200];
            }
            const int pb = ch * 16 + kk * 8 + c;
            #pragma unroll
            for (int mt = 0; mt < 3; ++mt) {
                uint32_t ah0 = smu[arow[mt][0] + pb];
                uint32_t ah1 = smu[arow[mt][1] + pb];
                uint32_t ah2 = smu[arow[mt][0] + pb + 4];
                uint32_t ah3 = smu[arow[mt][1] + pb + 4];
                #pragma unroll
                for (int d8 = 0; d8 < 3; ++d8) {
                    mma16(acc[mt][d8], ah0, ah1, ah2, ah3, bh0[d8], bh1[d8]);
                    mma16(acc[mt][d8], ah0, ah1, ah2, ah3, bl0[d8], bl1[d8]);
                }
            }
        }

        if (ch == 17) {
            const int db = dt * 192;
            #pragma unroll
            for (int mt = 0; mt < 3; ++mt) {
                int r0 = wm * 48 + mt * 16 + g, r1 = r0 + 8;
                #pragma unroll
                for (int d8 = 0; d8 < 3; ++d8) {
                    int col = db + wn * 24 + d8 * 8 + 2 * c;
                    if (r0 < 77)
                        *(float2*)(ob + (size_t)r0 * RS + col) =
                            make_float2(acc[mt][d8][0], acc[mt][d8][1]);
                    if (r1 < 77)
                        *(float2*)(ob + (size_t)r1 * RS + col) =
                            make_float2(acc[mt][d8][2], acc[mt][d8][3]);
                    #pragma unroll
                    for (int q = 0; q < 4; ++q) acc[mt][d8][q] = 0.f;
                }
            }
        }
        dt = ndt; ch = nch;
    }
}

extern "C" void kernel_launch(void* const* d_in, const int* in_sizes, int n_in,
                              void* d_out, int out_size) {
    const float* text   = (const float*)d_in[0];
    const float* vision = (const float*)d_in[1];
    if (n_in >= 2 && in_sizes[0] == VISION_ELEMS && in_sizes[1] == TEXT_ELEMS) {
        const float* t = text; text = vision; vision = t;
    }
    cudaFuncSetAttribute(k1_gemm1, cudaFuncAttributeMaxDynamicSharedMemorySize, K1_BYTES);
    cudaFuncSetAttribute(k3_gemm2, cudaFuncAttributeMaxDynamicSharedMemorySize, K3_BYTES);

    k1_gemm1<<<768, 512, K1_BYTES>>>(text, vision);
    k2_softmax<<<2464, 256>>>();
    k3_gemm2<<<256, 512, K3_BYTES>>>(vision, (float*)d_out);
}

// round 14
// speedup vs baseline: 1.1211x; 1.1211x over previous
#include <cuda_runtime.h>
#include <cuda_fp16.h>
#include <cstdint>

// ---------------- problem constants ----------------
constexpr int Dd   = 768;
constexpr int RS   = 256 * 768;            // row stride in floats (B*D)
constexpr int TEXT_ELEMS   = 77 * 256 * 768;
constexpr int VISION_ELEMS = 576 * 256 * 768;

// S / A scratch in gmem: [b][m=77][row container 576 words]
// before k2: fp32 logits; after k2: fp16 half2 pairs in [0,288) of each row
__device__ float g_S[256 * 77 * 576];

__device__ __forceinline__ float ex2f(float x) {
    float y; asm("ex2.approx.f32 %0, %1;" : "=f"(y) : "f"(x)); return y;
}

// split a float2 into hi (fp16x2) and lo (fp16x2 of residual), packed as u32
__device__ __forceinline__ void split2(float2 x, uint32_t& h, uint32_t& l) {
    __half hx = __float2half_rn(x.x), hy = __float2half_rn(x.y);
    __half lx = __float2half_rn(x.x - __half2float(hx));
    __half ly = __float2half_rn(x.y - __half2float(hy));
    h = (uint32_t)__half_as_ushort(hx) | ((uint32_t)__half_as_ushort(hy) << 16);
    l = (uint32_t)__half_as_ushort(lx) | ((uint32_t)__half_as_ushort(ly) << 16);
}

__device__ __forceinline__ uint32_t pack2(float2 x) {
    __half hx = __float2half_rn(x.x), hy = __float2half_rn(x.y);
    return (uint32_t)__half_as_ushort(hx) | ((uint32_t)__half_as_ushort(hy) << 16);
}

// fp16 m16n8k16, fp32 accumulate
__device__ __forceinline__ void mma16(float* c,
                                      uint32_t a0, uint32_t a1, uint32_t a2, uint32_t a3,
                                      uint32_t b0, uint32_t b1) {
    asm volatile(
        "mma.sync.aligned.m16n8k16.row.col.f32.f16.f16.f32 "
        "{%0,%1,%2,%3}, {%4,%5,%6,%7}, {%8,%9}, {%0,%1,%2,%3};\n"
        : "+f"(c[0]), "+f"(c[1]), "+f"(c[2]), "+f"(c[3])
        : "r"(a0), "r"(a1), "r"(a2), "r"(a3), "r"(b0), "r"(b1));
}

// ============== Kernel 1: S = T V^T (3xFP16), double-buffered, 2 CTAs/SM ==============
// grid 1536 = (b, nt of 6). M=96(77 real) x N=96 per CTA, 256 thr = 8 warps (2x4),
// warp tile 48x24. k-chunk = 32 floats (16 pairs).
// buffer layout (words): TH 0 (96x20) | TL 1920 | VH 3840 (96x20) | VL 5760; buf = 7680.
constexpr int K1_BUF   = 7680;             // words per buffer
constexpr int K1_BYTES = 2 * K1_BUF * 4;   // 61440 B -> 2 CTAs/SM

extern __shared__ float smdyn[];

__global__ __launch_bounds__(256, 2)
void k1_gemm1(const float* __restrict__ text, const float* __restrict__ vision) {
    uint32_t* smu = (uint32_t*)smdyn;
    const int b  = blockIdx.x / 6;
    const int nt = blockIdx.x % 6;
    const int nb = nt * 96;
    const float* tb = text + (size_t)b * Dd;
    const float* vb = vision + (size_t)b * Dd;

    const int tid  = threadIdx.x;
    const int w    = tid >> 5;    // 0..7
    const int lane = tid & 31;
    const int wm   = w >> 2;      // 0..1
    const int wn   = w & 3;       // 0..3
    const int g    = lane >> 2;
    const int c    = lane & 3;

    float acc[3][3][4];
    #pragma unroll
    for (int mt = 0; mt < 3; ++mt)
        #pragma unroll
        for (int nc = 0; nc < 3; ++nc)
            #pragma unroll
            for (int q = 0; q < 4; ++q) acc[mt][nc][q] = 0.f;

    float2 pT[5], pV[6];
    // prefetch chunk 0 (chunk = 32 floats = 16 pairs; 1 float2 = 1 pair)
    #pragma unroll
    for (int q = 0; q < 5; ++q) {
        int i = tid + 256 * q;            // T: 77 x 16 pairs = 1232
        if (i < 1232) {
            int m = i >> 4, j = i & 15;
            pT[q] = *(const float2*)(tb + (size_t)m * RS + 2 * j);
        }
    }
    #pragma unroll
    for (int q = 0; q < 6; ++q) {
        int i = tid + 256 * q;            // V: 96 x 16 = 1536
        int m = i >> 4, j = i & 15;
        pV[q] = *(const float2*)(vb + (size_t)(nb + m) * RS + 2 * j);
    }

    for (int dc = 0; dc < 24; ++dc) {
        const int bo = (dc & 1) * K1_BUF;

        // stage chunk dc into buf[dc&1]
        #pragma unroll
        for (int q = 0; q < 5; ++q) {
            int i = tid + 256 * q;
            if (i < 1232) {
                int m = i >> 4, j = i & 15;
                uint32_t h, l;
                split2(pT[q], h, l);
                smu[bo + m * 20 + j] = h;
                smu[bo + 1920 + m * 20 + j] = l;
            }
        }
        #pragma unroll
        for (int q = 0; q < 6; ++q) {
            int i = tid + 256 * q;
            int m = i >> 4, j = i & 15;
            uint32_t h, l;
            split2(pV[q], h, l);
            smu[bo + 3840 + m * 20 + j] = h;
            smu[bo + 5760 + m * 20 + j] = l;
        }

        // prefetch chunk dc+1 (consumed next iteration)
        if (dc < 23) {
            const int d0 = (dc + 1) * 32;
            #pragma unroll
            for (int q = 0; q < 5; ++q) {
                int i = tid + 256 * q;
                if (i < 1232) {
                    int m = i >> 4, j = i & 15;
                    pT[q] = *(const float2*)(tb + (size_t)m * RS + d0 + 2 * j);
                }
            }
            #pragma unroll
            for (int q = 0; q < 6; ++q) {
                int i = tid + 256 * q;
                int m = i >> 4, j = i & 15;
                pV[q] = *(const float2*)(vb + (size_t)(nb + m) * RS + d0 + 2 * j);
            }
        }

        __syncthreads();   // single barrier per interval

        // mma chunk dc from buf[dc&1]
        #pragma unroll
        for (int kk = 0; kk < 2; ++kk) {
            uint32_t bh0[3], bh1[3], bl0[3], bl1[3];
            #pragma unroll
            for (int nc = 0; nc < 3; ++nc) {
                int row = wn * 24 + nc * 8 + g;
                int ba  = bo + row * 20 + kk * 8 + c;
                bh0[nc] = smu[ba + 3840];     bh1[nc] = smu[ba + 3840 + 4];
                bl0[nc] = smu[ba + 5760];     bl1[nc] = smu[ba + 5760 + 4];
            }
            #pragma unroll
            for (int mt = 0; mt < 3; ++mt) {
                int r  = wm * 48 + mt * 16 + g;
                int aa = bo + r * 20 + kk * 8 + c;
                uint32_t ah0 = smu[aa];
                uint32_t ah1 = smu[aa + 8 * 20];
                uint32_t ah2 = smu[aa + 4];
                uint32_t ah3 = smu[aa + 8 * 20 + 4];
                uint32_t al0 = smu[aa + 1920];
                uint32_t al1 = smu[aa + 1920 + 8 * 20];
                uint32_t al2 = smu[aa + 1920 + 4];
                uint32_t al3 = smu[aa + 1920 + 8 * 20 + 4];
                #pragma unroll
                for (int nc = 0; nc < 3; ++nc) {
                    mma16(acc[mt][nc], ah0, ah1, ah2, ah3, bh0[nc], bh1[nc]);
                    mma16(acc[mt][nc], ah0, ah1, ah2, ah3, bl0[nc], bl1[nc]);
                    mma16(acc[mt][nc], al0, al1, al2, al3, bh0[nc], bh1[nc]);
                }
            }
        }
    }

    // epilogue: store S tile (fp32) to gmem scratch
    #pragma unroll
    for (int mt = 0; mt < 3; ++mt) {
        int r0 = wm * 48 + mt * 16 + g, r1 = r0 + 8;
        #pragma unroll
        for (int nc = 0; nc < 3; ++nc) {
            int col = nb + wn * 24 + nc * 8 + 2 * c;
            if (r0 < 77)
                *(float2*)&g_S[((size_t)b * 77 + r0) * 576 + col] =
                    make_float2(acc[mt][nc][0], acc[mt][nc][1]);
            if (r1 < 77)
                *(float2*)&g_S[((size_t)b * 77 + r1) * 576 + col] =
                    make_float2(acc[mt][nc][2], acc[mt][nc][3]);
        }
    }
}

// ===== Kernel 2: softmax (temp 0.07), in place; writes A as plain fp16 pairs =====
__global__ __launch_bounds__(256, 8)
void k2_softmax() {
    const int w = threadIdx.x >> 5, lane = threadIdx.x & 31;
    const int row = blockIdx.x * 8 + w;       // 0..19711
    float* p = &g_S[(size_t)row * 576];
    uint32_t* pu = (uint32_t*)p;
    const float SCL = 20.60992915555662f;     // log2(e)/0.07

    float v[18];
    float mx = -1e30f;
    #pragma unroll
    for (int j = 0; j < 18; ++j) { v[j] = p[lane + 32 * j]; mx = fmaxf(mx, v[j]); }
    #pragma unroll
    for (int o = 16; o > 0; o >>= 1) mx = fmaxf(mx, __shfl_xor_sync(0xffffffffu, mx, o));
    float sum = 0.f;
    #pragma unroll
    for (int j = 0; j < 18; ++j) { v[j] = ex2f((v[j] - mx) * SCL); sum += v[j]; }
    #pragma unroll
    for (int o = 16; o > 0; o >>= 1) sum += __shfl_xor_sync(0xffffffffu, sum, o);
    const float rinv = 1.0f / sum;

    // lane <-> pair transpose via shfl with warp-uniform register indices.
    #pragma unroll
    for (int q = 0; q < 9; ++q) {
        int s0 = (2 * lane) & 31;
        int s1 = (2 * lane + 1) & 31;
        float ea = __shfl_sync(0xffffffffu, v[2 * q],     s0);
        float eb = __shfl_sync(0xffffffffu, v[2 * q + 1], s0);
        float fa = __shfl_sync(0xffffffffu, v[2 * q],     s1);
        float fb = __shfl_sync(0xffffffffu, v[2 * q + 1], s1);
        float x = (lane < 16) ? ea : eb;
        float y = (lane < 16) ? fa : fb;
        pu[lane + 32 * q] = pack2(make_float2(x * rinv, y * rinv));  // fp16 plane [0,288)
    }
}

// ====== Kernel 3: O = A V (2xFP16: ah*bh + ah*bl), A fp16, d-tile 192, double-buffered ======
constexpr int A_STR   = 292;
constexpr int K3_VB   = 77 * A_STR + 12;       // 22496 (V buffers start)
constexpr int K3_BUF  = 6400;
constexpr int K3_BYTES = (K3_VB + 2 * K3_BUF) * 4;   // 141184 B

__global__ __launch_bounds__(512, 1)
void k3_gemm2(const float* __restrict__ vision, float* __restrict__ out) {
    uint32_t* smu = (uint32_t*)smdyn;
    const int b = blockIdx.x;
    const float* vb = vision + (size_t)b * Dd;
    float* ob = out + (size_t)b * Dd;

    const int tid  = threadIdx.x;
    const int w    = tid >> 5;    // 0..15  (n-pair owner for staging)
    const int lane = tid & 31;
    const int wm   = w >> 3;
    const int wn   = w & 7;
    const int g    = lane >> 2;
    const int c    = lane & 3;

    // load fp16 A into smem (coalesced float4): 77 rows x 72 float4
    {
        const float4* src = (const float4*)&g_S[(size_t)b * 77 * 576];
        #pragma unroll
        for (int q = 0; q < 11; ++q) {
            int i = tid + 512 * q;
            if (i < 5544) {                      // 77 * 72
                int m = i / 72, f = i % 72;
                *(float4*)&smdyn[m * A_STR + 4 * f] = src[(size_t)m * 144 + f];
            }
        }
    }

    int arow[3][2];
    #pragma unroll
    for (int mt = 0; mt < 3; ++mt) {
        int r0 = wm * 48 + mt * 16 + g;
        int r1 = r0 + 8;
        arow[mt][0] = (r0 > 76 ? 76 : r0) * A_STR;
        arow[mt][1] = (r1 > 76 ? 76 : r1) * A_STR;
    }

    float acc[3][3][4];
    #pragma unroll
    for (int mt = 0; mt < 3; ++mt)
        #pragma unroll
        for (int d8 = 0; d8 < 3; ++d8)
            #pragma unroll
            for (int q = 0; q < 4; ++q) acc[mt][d8][q] = 0.f;

    float pv0[6], pv1[6];
    {
        const float* r0p = vb + (size_t)(2 * w) * RS;
        const float* r1p = vb + (size_t)(2 * w + 1) * RS;
        #pragma unroll
        for (int it = 0; it < 6; ++it) {
            int d = lane + 32 * it;
            pv0[it] = r0p[d];
            pv1[it] = r1p[d];
        }
    }

    int dt = 0, ch = 0;
    for (int s = 0; s < 72; ++s) {
        const int bo = K3_VB + (s & 1) * K3_BUF;

        #pragma unroll
        for (int it = 0; it < 6; ++it) {
            int d = lane + 32 * it;
            uint32_t h, l;
            split2(make_float2(pv0[it], pv1[it]), h, l);
            smu[bo + w * 200 + d] = h;
            smu[bo + 3200 + w * 200 + d] = l;
        }

        int ndt = dt, nch = ch + 1;
        if (nch == 18) { nch = 0; ndt = dt + 1; }
        if (s < 71) {
            const float* r0p = vb + (size_t)(nch * 32 + 2 * w) * RS + ndt * 192;
            const float* r1p = r0p + RS;
            #pragma unroll
            for (int it = 0; it < 6; ++it) {
                int d = lane + 32 * it;
                pv0[it] = r0p[d];
                pv1[it] = r1p[d];
            }
        }

        __syncthreads();

        #pragma unroll
        for (int kk = 0; kk < 2; ++kk) {
            uint32_t bh0[3], bh1[3], bl0[3], bl1[3];
            #pragma unroll
            for (int d8 = 0; d8 < 3; ++d8) {
                int col = wn * 24 + d8 * 8 + g;
                int pa  = bo + (kk * 8 + c) * 200 + col;
                bh0[d8] = smu[pa];            bh1[d8] = smu[pa + 4 * 200];
                bl0[d8] = smu[pa + 3200];     bl1[d8] = smu[pa + 3200 + 4 * 200];
            }
            const int pb = ch * 16 + kk * 8 + c;
            #pragma unroll
            for (int mt = 0; mt < 3; ++mt) {
                uint32_t ah0 = smu[arow[mt][0] + pb];
                uint32_t ah1 = smu[arow[mt][1] + pb];
                uint32_t ah2 = smu[arow[mt][0] + pb + 4];
                uint32_t ah3 = smu[arow[mt][1] + pb + 4];
                #pragma unroll
                for (int d8 = 0; d8 < 3; ++d8) {
                    mma16(acc[mt][d8], ah0, ah1, ah2, ah3, bh0[d8], bh1[d8]);
                    mma16(acc[mt][d8], ah0, ah1, ah2, ah3, bl0[d8], bl1[d8]);
                }
            }
        }

        if (ch == 17) {
            const int db = dt * 192;
            #pragma unroll
            for (int mt = 0; mt < 3; ++mt) {
                int r0 = wm * 48 + mt * 16 + g, r1 = r0 + 8;
                #pragma unroll
                for (int d8 = 0; d8 < 3; ++d8) {
                    int col = db + wn * 24 + d8 * 8 + 2 * c;
                    if (r0 < 77)
                        *(float2*)(ob + (size_t)r0 * RS + col) =
                            make_float2(acc[mt][d8][0], acc[mt][d8][1]);
                    if (r1 < 77)
                        *(float2*)(ob + (size_t)r1 * RS + col) =
                            make_float2(acc[mt][d8][2], acc[mt][d8][3]);
                    #pragma unroll
                    for (int q = 0; q < 4; ++q) acc[mt][d8][q] = 0.f;
                }
            }
        }
        dt = ndt; ch = nch;
    }
}

extern "C" void kernel_launch(void* const* d_in, const int* in_sizes, int n_in,
                              void* d_out, int out_size) {
    const float* text   = (const float*)d_in[0];
    const float* vision = (const float*)d_in[1];
    if (n_in >= 2 && in_sizes[0] == VISION_ELEMS && in_sizes[1] == TEXT_ELEMS) {
        const float* t = text; text = vision; vision = t;
    }
    cudaFuncSetAttribute(k1_gemm1, cudaFuncAttributeMaxDynamicSharedMemorySize, K1_BYTES);
    cudaFuncSetAttribute(k3_gemm2, cudaFuncAttributeMaxDynamicSharedMemorySize, K3_BYTES);

    k1_gemm1<<<1536, 256, K1_BYTES>>>(text, vision);
    k2_softmax<<<2464, 256>>>();
    k3_gemm2<<<256, 512, K3_BYTES>>>(vision, (float*)d_out);
}